// round 3
// baseline (speedup 1.0000x reference)
#include <cuda_runtime.h>
#include <cstdint>

#define Bb   32
#define Tt   2048
#define Hh   256
#define G3   768
#define NVv  18
#define NOo  17
#define CL   8        // CTAs per cluster
#define NT   384      // threads per scan CTA
#define COLS 96       // gate columns per CTA
#define HPC  32       // h outputs per CTA

__device__ float g_hout[Bb * Tt * Hh];   // h states for the head GEMM

// ---------------- helpers ----------------
__device__ __forceinline__ unsigned smem_u32(const void* p) {
    return (unsigned)__cvta_generic_to_shared(p);
}
__device__ __forceinline__ unsigned mapa_u32(unsigned local, int rank) {
    unsigned r;
    asm("mapa.shared::cluster.u32 %0, %1, %2;" : "=r"(r) : "r"(local), "r"(rank));
    return r;
}
__device__ __forceinline__ unsigned long long pack2(float lo, float hi) {
    unsigned long long v;
    asm("mov.b64 %0, {%1, %2};" : "=l"(v) : "f"(lo), "f"(hi));
    return v;
}
__device__ __forceinline__ float2 unpack2(unsigned long long v) {
    float lo, hi;
    asm("mov.b64 {%0, %1}, %2;" : "=f"(lo), "=f"(hi) : "l"(v));
    return make_float2(lo, hi);
}
__device__ __forceinline__ unsigned long long fma2(unsigned long long a,
                                                   unsigned long long b,
                                                   unsigned long long c) {
    unsigned long long d;
    asm("fma.rn.f32x2 %0, %1, %2, %3;" : "=l"(d) : "l"(a), "l"(b), "l"(c));
    return d;
}
__device__ __forceinline__ float fast_sigmoid(float x) {
    float e;
    asm("ex2.approx.f32 %0, %1;" : "=f"(e) : "f"(-1.4426950408889634f * x));
    float r;
    asm("rcp.approx.f32 %0, %1;" : "=f"(r) : "f"(1.0f + e));
    return r;
}
__device__ __forceinline__ float fast_tanh(float x) {
    return fmaf(2.0f, fast_sigmoid(2.0f * x), -1.0f);
}
__device__ __forceinline__ void mbar_arm(unsigned m, unsigned bytes) {
    asm volatile("mbarrier.arrive.expect_tx.shared.b64 _, [%0], %1;"
                 :: "r"(m), "r"(bytes) : "memory");
}
__device__ __forceinline__ void mbar_wait(unsigned m, unsigned par) {
    unsigned done;
    do {
        asm volatile(
            "{\n\t.reg .pred P;\n\t"
            "mbarrier.try_wait.parity.acquire.cluster.shared::cta.b64 P, [%1], %2, 0x989680;\n\t"
            "selp.b32 %0, 1, 0, P;\n\t}"
            : "=r"(done) : "r"(m), "r"(par) : "memory");
    } while (!done);
}

// ---------------- kernel 1: GRU scan ----------------
// 16 clusters x 8 CTAs; each cluster runs TWO batches interleaved.
// CTA rank owns gate cols { g*256 + rank*32 + j : g in 0..2, j in 0..31 } over full K=256.
// Thread: cp = t0%48 -> col pair c0=2cp; kq = t0/48 -> k rows [32kq, 32kq+32).
__global__ __launch_bounds__(NT, 1) __cluster_dims__(CL, 1, 1)
void scan_kernel(const int* __restrict__ tokens,
                 const float* __restrict__ embed,
                 const float* __restrict__ W_ih,
                 const float* __restrict__ b_ih,
                 const float* __restrict__ W_hh,
                 const float* __restrict__ b_hh,
                 float* __restrict__ betas) {
    __shared__ int tok_s[2][Tt];
    __shared__ __align__(16) float part[2][8][COLS];               // [batch][kq][col]
    __shared__ __align__(16) unsigned long long hbuf[2][2][Hh/2];  // [batch][pp][128]
    __shared__ float G_s[NVv * COLS];
    __shared__ float bhh_s[COLS];
    __shared__ __align__(8) unsigned long long mbar[2][2];         // [batch][pp]

    const int t0   = threadIdx.x;
    const int rank = blockIdx.x & (CL - 1);
    const int cl   = blockIdx.x >> 3;
    const int bA   = 2 * cl;

    const int cp = t0 % 48;
    const int kq = t0 / 48;
    const int c0 = 2 * cp;                                // local col (even)
    const int C0 = (c0 >> 5) * 256 + rank * HPC + (c0 & 31);
    const int C1 = C0 + 1;                                // same 32-group (c0 even)

    // ---- prologue smem loads
    for (int i = t0; i < 2 * Tt; i += NT) {
        int b = i >> 11, k = i & (Tt - 1);
        tok_s[b][k] = tokens[(bA + b) * Tt + k];
    }
    if (t0 < COLS) {
        int C = (t0 >> 5) * 256 + rank * HPC + (t0 & 31);
        bhh_s[t0] = b_hh[C];
    }
    if (t0 < Hh / 2) { hbuf[0][0][t0] = 0ULL; hbuf[1][0][t0] = 0ULL; }
    if (t0 == 0) {
        #pragma unroll
        for (int b = 0; b < 2; b++)
            #pragma unroll
            for (int pp = 0; pp < 2; pp++)
                asm volatile("mbarrier.init.shared.b64 [%0], 1;"
                             :: "r"(smem_u32(&mbar[b][pp])) : "memory");
    }

    unsigned long long w0[16], w1[16];

    // ---- G table: G[v][c] = embed[v] . W_ih[:,C] + b_ih[C], via register GEMM
    {
        const float* Wb = W_ih + (size_t)(kq * 32) * G3;
        #pragma unroll
        for (int kk = 0; kk < 16; kk++) {
            w0[kk] = pack2(Wb[(2 * kk) * G3 + C0], Wb[(2 * kk + 1) * G3 + C0]);
            w1[kk] = pack2(Wb[(2 * kk) * G3 + C1], Wb[(2 * kk + 1) * G3 + C1]);
        }
    }
    __syncthreads();
    for (int v = 0; v < NVv; v++) {
        const float* ev = embed + v * Hh + kq * 32;
        unsigned long long acc0 = 0ULL, acc1 = 0ULL;
        #pragma unroll
        for (int kk = 0; kk < 16; kk++) {
            unsigned long long h2 = pack2(ev[2 * kk], ev[2 * kk + 1]);
            acc0 = fma2(w0[kk], h2, acc0);
            acc1 = fma2(w1[kk], h2, acc1);
        }
        float2 a0 = unpack2(acc0), a1 = unpack2(acc1);
        *(float2*)&part[1][kq][c0] = make_float2(a0.x + a0.y, a1.x + a1.y);
        __syncthreads();
        if (t0 < COLS) {
            int C = (t0 >> 5) * 256 + rank * HPC + (t0 & 31);
            float s = b_ih[C];
            #pragma unroll
            for (int q = 0; q < 8; q++) s += part[1][q][t0];
            G_s[v * COLS + t0] = s;
        }
        __syncthreads();
    }

    // ---- W_hh into registers
    {
        const float* Wb = W_hh + (size_t)(kq * 32) * G3;
        #pragma unroll
        for (int kk = 0; kk < 16; kk++) {
            w0[kk] = pack2(Wb[(2 * kk) * G3 + C0], Wb[(2 * kk + 1) * G3 + C0]);
            w1[kk] = pack2(Wb[(2 * kk) * G3 + C1], Wb[(2 * kk + 1) * G3 + C1]);
        }
    }

    // ---- arm phases for t=0 and t=1 (before any cross-CTA traffic is possible)
    if (t0 == 0) {
        mbar_arm(smem_u32(&mbar[0][0]), 1024);
        mbar_arm(smem_u32(&mbar[0][1]), 1024);
        mbar_arm(smem_u32(&mbar[1][0]), 1024);
        mbar_arm(smem_u32(&mbar[1][1]), 1024);
    }
    __syncthreads();
    asm volatile("barrier.cluster.arrive.aligned;" ::: "memory");
    asm volatile("barrier.cluster.wait.aligned;"   ::: "memory");

    // ---- cluster addresses (affine mapa + constant smem offsets)
    const unsigned ref = smem_u32(&hbuf[0][0][0]);
    unsigned base[CL];
    #pragma unroll
    for (int r2 = 0; r2 < CL; r2++) base[r2] = mapa_u32(ref, r2);
    unsigned hoff[2][2], moff[2][2];
    #pragma unroll
    for (int b = 0; b < 2; b++)
        #pragma unroll
        for (int pp = 0; pp < 2; pp++) {
            hoff[b][pp] = smem_u32(&hbuf[b][pp][0]) - ref;
            moff[b][pp] = smem_u32(&mbar[b][pp]) - ref;
        }

    float* ob[2] = { betas  + (size_t)bA * Tt * Hh, betas  + (size_t)(bA + 1) * Tt * Hh };
    float* oh[2] = { g_hout + (size_t)bA * Tt * Hh, g_hout + (size_t)(bA + 1) * Tt * Hh };
    const int gidx = rank * HPC + t0;   // valid for t0 < 32

    for (int t = 0; t < Tt; t++) {
        const int p = t & 1;
        const unsigned par = (t >> 1) & 1;

        #pragma unroll
        for (int b = 0; b < 2; b++) {
            // ---- gate partial sums over my k-slice
            unsigned long long acc0 = 0ULL, acc1 = 0ULL;
            const ulonglong2* hb = (const ulonglong2*)&hbuf[b][p][kq * 16];
            #pragma unroll
            for (int q = 0; q < 8; q++) {
                ulonglong2 hv = hb[q];
                acc0 = fma2(w0[2 * q],     hv.x, acc0);
                acc1 = fma2(w1[2 * q],     hv.x, acc1);
                acc0 = fma2(w0[2 * q + 1], hv.y, acc0);
                acc1 = fma2(w1[2 * q + 1], hv.y, acc1);
            }
            float2 a0 = unpack2(acc0), a1 = unpack2(acc1);
            *(float2*)&part[b][kq][c0] = make_float2(a0.x + a0.y, a1.x + a1.y);
            __syncthreads();

            // ---- epilogue: 32 threads -> this CTA's 32 new h values
            if (t0 < HPC) {
                const int j = t0;
                float sr = bhh_s[j], sz = bhh_s[32 + j], sn = bhh_s[64 + j];
                #pragma unroll
                for (int q = 0; q < 8; q++) {
                    sr += part[b][q][j];
                    sz += part[b][q][32 + j];
                    sn += part[b][q][64 + j];
                }
                const int tok = tok_s[b][t];
                const float* Gr = &G_s[tok * COLS];
                float r  = fast_sigmoid(Gr[j] + sr);
                float z  = fast_sigmoid(Gr[32 + j] + sz);
                float n  = fast_tanh(fmaf(r, sn, Gr[64 + j]));
                float ho = ((const float*)&hbuf[b][p][0])[gidx];
                float hn = fmaf(z, ho - n, n);

                const unsigned ho2 = hoff[b][p ^ 1] + 4u * gidx;
                const unsigned mo2 = moff[b][p];
                #pragma unroll
                for (int r2 = 0; r2 < CL; r2++) {
                    asm volatile(
                        "st.async.shared::cluster.mbarrier::complete_tx::bytes.b32 [%0], %1, [%2];"
                        :: "r"(base[r2] + ho2), "f"(hn), "r"(base[r2] + mo2) : "memory");
                }
                ob[b][(size_t)t * Hh + gidx] = z;
                oh[b][(size_t)t * Hh + gidx] = hn;
            }
        }

        // ---- wait for both batches' h broadcasts; re-arm for step t+2
        #pragma unroll
        for (int b = 0; b < 2; b++) {
            const unsigned m = smem_u32(&mbar[b][p]);
            mbar_wait(m, par);
            if (t0 == 0) mbar_arm(m, 1024);
        }
    }
}

// ---------------- kernel 2: head GEMM (2 rows per thread) ----------------
__global__ __launch_bounds__(256) void head_kernel(const float* __restrict__ W_head,
                                                   const float* __restrict__ b_head,
                                                   float* __restrict__ logits) {
    __shared__ float w_s[NOo * Hh];   // transposed: w_s[o*H + k]
    __shared__ float b_s[NOo];
    for (int i = threadIdx.x; i < NOo * Hh; i += blockDim.x) {
        int o = i / Hh, k = i - o * Hh;
        w_s[i] = W_head[k * NOo + o];
    }
    if (threadIdx.x < NOo) b_s[threadIdx.x] = b_head[threadIdx.x];
    __syncthreads();

    const int gid = blockIdx.x * blockDim.x + threadIdx.x;
    const float4* h0 = (const float4*)(g_hout + (size_t)(2 * gid) * Hh);
    const float4* h1 = (const float4*)(g_hout + (size_t)(2 * gid + 1) * Hh);
    float a0[NOo], a1[NOo];
    #pragma unroll
    for (int o = 0; o < NOo; o++) { a0[o] = b_s[o]; a1[o] = b_s[o]; }
    for (int k4 = 0; k4 < Hh / 4; k4++) {
        float4 v0 = h0[k4], v1 = h1[k4];
        #pragma unroll
        for (int o = 0; o < NOo; o++) {
            const float4 wv = *(const float4*)&w_s[o * Hh + 4 * k4];
            a0[o] = fmaf(v0.x, wv.x, fmaf(v0.y, wv.y, fmaf(v0.z, wv.z, fmaf(v0.w, wv.w, a0[o]))));
            a1[o] = fmaf(v1.x, wv.x, fmaf(v1.y, wv.y, fmaf(v1.z, wv.z, fmaf(v1.w, wv.w, a1[o]))));
        }
    }
    float* o0 = logits + (size_t)(2 * gid) * NOo;
    float* o1 = logits + (size_t)(2 * gid + 1) * NOo;
    #pragma unroll
    for (int o = 0; o < NOo; o++) { o0[o] = a0[o]; o1[o] = a1[o]; }
}

// ---------------- launch ----------------
extern "C" void kernel_launch(void* const* d_in, const int* in_sizes, int n_in,
                              void* d_out, int out_size) {
    const int*   tokens = (const int*)d_in[0];
    const float* embed  = (const float*)d_in[1];
    const float* W_ih   = (const float*)d_in[2];
    const float* W_hh   = (const float*)d_in[3];
    const float* b_ih   = (const float*)d_in[4];
    const float* b_hh   = (const float*)d_in[5];
    const float* W_head = (const float*)d_in[6];
    const float* b_head = (const float*)d_in[7];
    (void)in_sizes; (void)n_in; (void)out_size;

    float* out    = (float*)d_out;
    float* logits = out;                          // [B*T, 17]
    float* betas  = out + (size_t)Bb * Tt * NOo;  // [B*T, 256]

    scan_kernel<<<16 * CL, NT>>>(tokens, embed, W_ih, b_ih, W_hh, b_hh, betas);
    head_kernel<<<(Bb * Tt) / 512, 256>>>(W_head, b_head, logits);
}

// round 4
// speedup vs baseline: 2.5398x; 2.5398x over previous
#include <cuda_runtime.h>
#include <cstdint>

#define Bb   32
#define Tt   2048
#define Hh   256
#define G3   768
#define NVv  18
#define NOo  17
#define CL   4       // CTAs per cluster (one cluster per batch)
#define NT   384     // threads per scan CTA
#define NCTA (Bb * CL)

__device__ float g_hout[Bb * Tt * Hh];   // h states for the head GEMM

// ---------------- helpers ----------------
__device__ __forceinline__ unsigned smem_u32(const void* p) {
    return (unsigned)__cvta_generic_to_shared(p);
}
__device__ __forceinline__ unsigned mapa_u32(unsigned local, int rank) {
    unsigned r;
    asm("mapa.shared::cluster.u32 %0, %1, %2;" : "=r"(r) : "r"(local), "r"(rank));
    return r;
}
__device__ __forceinline__ unsigned long long pack2(float lo, float hi) {
    unsigned long long v;
    asm("mov.b64 %0, {%1, %2};" : "=l"(v) : "f"(lo), "f"(hi));
    return v;
}
__device__ __forceinline__ float2 unpack2(unsigned long long v) {
    float lo, hi;
    asm("mov.b64 {%0, %1}, %2;" : "=f"(lo), "=f"(hi) : "l"(v));
    return make_float2(lo, hi);
}
__device__ __forceinline__ unsigned long long fma2(unsigned long long a,
                                                   unsigned long long b,
                                                   unsigned long long c) {
    unsigned long long d;
    asm("fma.rn.f32x2 %0, %1, %2, %3;" : "=l"(d) : "l"(a), "l"(b), "l"(c));
    return d;
}
__device__ __forceinline__ float fast_sigmoid(float x) {
    float e;
    asm("ex2.approx.f32 %0, %1;" : "=f"(e) : "f"(-1.4426950408889634f * x));
    float r;
    asm("rcp.approx.f32 %0, %1;" : "=f"(r) : "f"(1.0f + e));
    return r;
}
__device__ __forceinline__ float fast_tanh(float x) {
    return fmaf(2.0f, fast_sigmoid(2.0f * x), -1.0f);
}
__device__ __forceinline__ void mbar_arm(unsigned m, unsigned bytes) {
    asm volatile("mbarrier.arrive.expect_tx.shared.b64 _, [%0], %1;"
                 :: "r"(m), "r"(bytes) : "memory");
}
__device__ __forceinline__ void mbar_wait(unsigned m, unsigned par) {
    unsigned done;
    do {
        asm volatile(
            "{\n\t.reg .pred P;\n\t"
            "mbarrier.try_wait.parity.acquire.cluster.shared::cta.b64 P, [%1], %2, 0x989680;\n\t"
            "selp.b32 %0, 1, 0, P;\n\t}"
            : "=r"(done) : "r"(m), "r"(par) : "memory");
    } while (!done);
}

// ---------------- kernel 1: GRU scan ----------------
// 32 clusters x 4 CTAs, one batch per cluster (round-2 partitioning):
// CTA rank owns gate cols { g*256 + 64*rank + j } over FULL K=256; produces
// h slice [64*rank, 64*rank+64). Thread: cp=t0%96 (2 cols), kq=t0/96 (k-quarter).
// Per step: early-FMA(own k-chunk) -> mbar wait (remote h) -> FMA(rest) ->
// sync -> 192-thr gate sums -> sync -> 64-thr activations + local st.shared +
// 3x st.async -> sync.
__global__ __launch_bounds__(NT, 1) __cluster_dims__(CL, 1, 1)
void scan_kernel(const int* __restrict__ tokens,
                 const float* __restrict__ embed,
                 const float* __restrict__ W_ih,
                 const float* __restrict__ b_ih,
                 const float* __restrict__ W_hh,
                 const float* __restrict__ b_hh,
                 float* __restrict__ betas) {
    __shared__ float G_s[NVv * 192];
    __shared__ float embed_s[NVv * Hh];
    __shared__ int   tok_s[Tt];
    __shared__ __align__(16) float part[4][192];      // [kq][col]
    __shared__ float gsum[192];
    __shared__ __align__(16) unsigned long long hbuf[2][Hh / 2];
    __shared__ float bhh_s[192];
    __shared__ __align__(8) unsigned long long mbar[2];

    const int t0    = threadIdx.x;
    const int rank  = blockIdx.x & (CL - 1);
    const int batch = blockIdx.x >> 2;
    const int cp    = t0 % 96;
    const int kq    = t0 / 96;                         // warp-uniform (96 = 3 warps)
    const int c0    = 2 * cp;
    const int C0    = ((c0 >> 6) << 8) + (rank << 6) + (c0 & 63);
    const int C1    = C0 + 1;

    // ---- prologue
    for (int i = t0; i < NVv * Hh; i += NT) embed_s[i] = embed[i];
    for (int i = t0; i < 192; i += NT) {
        int g = i >> 6, j = i & 63;
        bhh_s[i] = b_hh[(g << 8) + (rank << 6) + j];
    }
    for (int i = t0; i < Tt; i += NT) tok_s[i] = tokens[batch * Tt + i];
    if (t0 < Hh / 2) hbuf[0][t0] = 0ULL;              // h0 = 0
    if (t0 == 0) {
        asm volatile("mbarrier.init.shared.b64 [%0], 1;" :: "r"(smem_u32(&mbar[0])) : "memory");
        asm volatile("mbarrier.init.shared.b64 [%0], 1;" :: "r"(smem_u32(&mbar[1])) : "memory");
    }
    __syncthreads();

    // ---- G table: G[v][c] = embed[v] . W_ih[:,C] + b_ih[C]
    {
        float acc[9]; int Cg[9]; int vv[9];
        #pragma unroll
        for (int i = 0; i < 9; i++) {
            int e = t0 + i * NT;
            int v = e / 192, c = e - v * 192;
            int C = ((c >> 6) << 8) + (rank << 6) + (c & 63);
            acc[i] = b_ih[C]; Cg[i] = C; vv[i] = v * Hh;
        }
        for (int k = 0; k < Hh; k++) {
            const float* Wk = W_ih + (size_t)k * G3;
            #pragma unroll
            for (int i = 0; i < 9; i++)
                acc[i] = fmaf(embed_s[vv[i] + k], Wk[Cg[i]], acc[i]);
        }
        #pragma unroll
        for (int i = 0; i < 9; i++) {
            int e = t0 + i * NT;
            int v = e / 192, c = e - v * 192;
            G_s[v * 192 + c] = acc[i];
        }
    }

    // ---- W_hh into registers: 2 cols x 64 k (32 f32x2 pairs each)
    unsigned long long w0[32], w1[32];
    {
        const float* Wb = W_hh + (size_t)(kq * 64) * G3;
        #pragma unroll
        for (int kk = 0; kk < 32; kk++) {
            w0[kk] = pack2(Wb[(2 * kk) * G3 + C0], Wb[(2 * kk + 1) * G3 + C0]);
            w1[kk] = pack2(Wb[(2 * kk) * G3 + C1], Wb[(2 * kk + 1) * G3 + C1]);
        }
    }

    // ---- arm: mbar[1] guards h_1 (waited at t=1), mbar[0] guards h_2 (t=2)
    if (t0 == 0) {
        mbar_arm(smem_u32(&mbar[1]), 768);
        mbar_arm(smem_u32(&mbar[0]), 768);
    }
    __syncthreads();
    asm volatile("barrier.cluster.arrive.aligned;" ::: "memory");
    asm volatile("barrier.cluster.wait.aligned;"   ::: "memory");

    // ---- cluster addresses
    const unsigned ref = smem_u32(&hbuf[0][0]);
    unsigned base[CL];
    #pragma unroll
    for (int r2 = 0; r2 < CL; r2++) base[r2] = mapa_u32(ref, r2);
    unsigned hoff[2], moff[2];
    #pragma unroll
    for (int pp = 0; pp < 2; pp++) {
        hoff[pp] = smem_u32(&hbuf[pp][0]) - ref;
        moff[pp] = smem_u32(&mbar[pp]) - ref;
    }

    float* out_beta = betas  + (size_t)(batch * Tt) * Hh + (rank << 6);
    float* out_h    = g_hout + (size_t)(batch * Tt) * Hh + (rank << 6);
    const int gidx  = (rank << 6) + t0;   // valid for t0 < 64

    unsigned par0 = 0, par1 = 0;

    for (int t = 0; t < Tt; t++) {
        const int pc = t & 1;          // h_t lives in hbuf[pc]
        const int pn = pc ^ 1;         // h_{t+1} goes to hbuf[pn], mbar[pn]
        const int tok = tok_s[t];

        // ---- early FMA: own k-chunk (local data; guarded by last iter's sync)
        unsigned long long acc0 = 0ULL, acc1 = 0ULL;
        if (kq == rank) {
            const ulonglong2* hb = (const ulonglong2*)&hbuf[pc][kq << 5];
            #pragma unroll
            for (int q = 0; q < 16; q++) {
                ulonglong2 hv = hb[q];
                acc0 = fma2(w0[2 * q],     hv.x, acc0);
                acc1 = fma2(w1[2 * q],     hv.x, acc1);
                acc0 = fma2(w0[2 * q + 1], hv.y, acc0);
                acc1 = fma2(w1[2 * q + 1], hv.y, acc1);
            }
            float2 a0 = unpack2(acc0), a1 = unpack2(acc1);
            *(float2*)&part[kq][c0] = make_float2(a0.x + a0.y, a1.x + a1.y);
        }

        // ---- wait for remote h slices of step t (t>=1), re-arm for t+2
        if (t > 0) {
            const unsigned m = smem_u32(&mbar[pc]);
            mbar_wait(m, pc ? par1 : par0);
            if (pc) par1 ^= 1; else par0 ^= 1;
            if (t0 == 0) mbar_arm(m, 768);
        }

        // ---- remaining FMA chunks
        if (kq != rank) {
            const ulonglong2* hb = (const ulonglong2*)&hbuf[pc][kq << 5];
            #pragma unroll
            for (int q = 0; q < 16; q++) {
                ulonglong2 hv = hb[q];
                acc0 = fma2(w0[2 * q],     hv.x, acc0);
                acc1 = fma2(w1[2 * q],     hv.x, acc1);
                acc0 = fma2(w0[2 * q + 1], hv.y, acc0);
                acc1 = fma2(w1[2 * q + 1], hv.y, acc1);
            }
            float2 a0 = unpack2(acc0), a1 = unpack2(acc1);
            *(float2*)&part[kq][c0] = make_float2(a0.x + a0.y, a1.x + a1.y);
        }
        __syncthreads();

        // ---- phase A: 192 threads, one gate-column sum each
        if (t0 < 192) {
            gsum[t0] = bhh_s[t0] + ((part[0][t0] + part[1][t0]) +
                                    (part[2][t0] + part[3][t0]));
        }
        __syncthreads();

        // ---- phase B: 64 threads, activations + h update + broadcast
        if (t0 < 64) {
            const int j = t0;
            const float* Gr = &G_s[tok * 192];
            float r  = fast_sigmoid(Gr[j] + gsum[j]);
            float z  = fast_sigmoid(Gr[64 + j] + gsum[64 + j]);
            float n  = fast_tanh(fmaf(r, gsum[128 + j], Gr[128 + j]));
            float ho = ((const float*)&hbuf[pc][0])[gidx];
            float hn = fmaf(z, ho - n, n);

            // local slice store (no DSMEM for self)
            ((float*)&hbuf[pn][0])[gidx] = hn;
            // 3 remote sends -> peers' hbuf[pn] + mbar[pn]
            const unsigned ho2 = hoff[pn] + 4u * gidx;
            const unsigned mo2 = moff[pn];
            #pragma unroll
            for (int r2 = 0; r2 < CL; r2++) {
                if (r2 != rank) {
                    asm volatile(
                        "st.async.shared::cluster.mbarrier::complete_tx::bytes.b32 [%0], %1, [%2];"
                        :: "r"(base[r2] + ho2), "f"(hn), "r"(base[r2] + mo2) : "memory");
                }
            }
            out_beta[(size_t)t * Hh + j] = z;
            out_h[(size_t)t * Hh + j]    = hn;
        }
        __syncthreads();
    }

    // ensure in-flight st.async to peers land before any CTA exits
    asm volatile("barrier.cluster.arrive.aligned;" ::: "memory");
    asm volatile("barrier.cluster.wait.aligned;"   ::: "memory");
}

// ---------------- kernel 2: head GEMM (k-split x2 + shfl reduce) ----------------
__global__ __launch_bounds__(256) void head_kernel(const float* __restrict__ W_head,
                                                   const float* __restrict__ b_head,
                                                   float* __restrict__ logits) {
    __shared__ float w_s[NOo * Hh];   // transposed: w_s[o*H + k]
    __shared__ float b_s[NOo];
    for (int i = threadIdx.x; i < NOo * Hh; i += blockDim.x) {
        int o = i / Hh, k = i - o * Hh;
        w_s[i] = W_head[k * NOo + o];
    }
    if (threadIdx.x < NOo) b_s[threadIdx.x] = b_head[threadIdx.x];
    __syncthreads();

    const int gid = blockIdx.x * blockDim.x + threadIdx.x;
    const int row = gid >> 1;
    const int s   = gid & 1;          // k-half
    const float4* hr = (const float4*)(g_hout + (size_t)row * Hh) + s * 32;

    float acc[NOo];
    #pragma unroll
    for (int o = 0; o < NOo; o++) acc[o] = 0.0f;
    for (int k4 = 0; k4 < 32; k4++) {
        float4 hv = hr[k4];
        const int kb = s * 128 + 4 * k4;
        #pragma unroll
        for (int o = 0; o < NOo; o++) {
            const float4 wv = *(const float4*)&w_s[o * Hh + kb];
            acc[o] = fmaf(hv.x, wv.x, fmaf(hv.y, wv.y, fmaf(hv.z, wv.z, fmaf(hv.w, wv.w, acc[o]))));
        }
    }
    #pragma unroll
    for (int o = 0; o < NOo; o++)
        acc[o] += __shfl_xor_sync(0xFFFFFFFFu, acc[o], 1);
    if (s == 0) {
        float* out = logits + (size_t)row * NOo;
        #pragma unroll
        for (int o = 0; o < NOo; o++) out[o] = acc[o] + b_s[o];
    }
}

// ---------------- launch ----------------
extern "C" void kernel_launch(void* const* d_in, const int* in_sizes, int n_in,
                              void* d_out, int out_size) {
    const int*   tokens = (const int*)d_in[0];
    const float* embed  = (const float*)d_in[1];
    const float* W_ih   = (const float*)d_in[2];
    const float* W_hh   = (const float*)d_in[3];
    const float* b_ih   = (const float*)d_in[4];
    const float* b_hh   = (const float*)d_in[5];
    const float* W_head = (const float*)d_in[6];
    const float* b_head = (const float*)d_in[7];
    (void)in_sizes; (void)n_in; (void)out_size;

    float* out    = (float*)d_out;
    float* logits = out;                          // [B*T, 17]
    float* betas  = out + (size_t)Bb * Tt * NOo;  // [B*T, 256]

    scan_kernel<<<NCTA, NT>>>(tokens, embed, W_ih, b_ih, W_hh, b_hh, betas);
    head_kernel<<<(Bb * Tt * 2) / 256, 256>>>(W_head, b_head, logits);
}